// round 17
// baseline (speedup 1.0000x reference)
#include <cuda_runtime.h>
#include <cuda_fp16.h>
#include <cstdint>

// ActuatorNet, round 17: 2-term fp16 W-split on ALL hidden layers.
//   D = Ahi*Whi + Ahi*Wlo   (A quantized once to fp16; W exact to ~2^-22)
// Why: R14/R15/R16 calibration shows NO inter-layer attenuation (c~1);
// per-layer error = A-quant + W-quant sources, roughly equal & incoherent
// (sqrt(19*2)*1.4e-4 = 9.5e-4 == measured R14). Removing the W source:
// E = 9.55e-4*sqrt(f), f in [0.3,0.7] -> 5.2e-4..8.0e-4: passes across
// the whole plausible range. Epilogue unchanged from R14 (ss_pack only).

#define NTHREADS 256
#define NWARPS   8

typedef unsigned long long u64;

// smem layout (bytes)
#define SM_FRAG   0                      // 19*16*32 u64 = 77824 (hi+lo)
#define SM_W1     77824                  // 192 f32
#define SM_B1     (SM_W1 + 768)          // 32 f32
#define SM_BH     (SM_B1 + 128)          // 19*32 f32 = 2432
#define SM_WOUT   (SM_BH + 2432)         // 32 f32
#define SM_BOUT   (SM_WOUT + 128)        // 1 f32
#define SM_TOTAL  (SM_BOUT + 16)         // ~81.2 KB -> 2 CTAs/SM

__device__ __forceinline__ uint32_t cvt_f16x2(float hi_elem, float lo_elem) {
    uint32_t r;
    asm("cvt.rn.f16x2.f32 %0, %1, %2;" : "=r"(r) : "f"(hi_elem), "f"(lo_elem));
    return r;
}

// d += a*b   (fp16 inputs, f32 accumulate)
__device__ __forceinline__ void mma_f16(float* d,
                                        uint32_t a0, uint32_t a1,
                                        uint32_t a2, uint32_t a3,
                                        uint32_t b0, uint32_t b1) {
    asm volatile(
        "mma.sync.aligned.m16n8k16.row.col.f32.f16.f16.f32 "
        "{%0,%1,%2,%3}, {%4,%5,%6,%7}, {%8,%9}, {%0,%1,%2,%3};"
        : "+f"(d[0]), "+f"(d[1]), "+f"(d[2]), "+f"(d[3])
        : "r"(a0), "r"(a1), "r"(a2), "r"(a3), "r"(b0), "r"(b1));
}

// d = a*b + {cx,cy,cx,cy}
__device__ __forceinline__ void mma_f16_init(float* d,
                                             uint32_t a0, uint32_t a1,
                                             uint32_t a2, uint32_t a3,
                                             uint32_t b0, uint32_t b1,
                                             float cx, float cy) {
    asm volatile(
        "mma.sync.aligned.m16n8k16.row.col.f32.f16.f16.f32 "
        "{%0,%1,%2,%3}, {%4,%5,%6,%7}, {%8,%9}, {%10,%11,%10,%11};"
        : "=f"(d[0]), "=f"(d[1]), "=f"(d[2]), "=f"(d[3])
        : "r"(a0), "r"(a1), "r"(a2), "r"(a3), "r"(b0), "r"(b1),
          "f"(cx), "f"(cy));
}

__device__ __forceinline__ float softsign_f(float v) {
    return __fdividef(v, 1.0f + fabsf(v));
}

// fp32 softsign on raw preact, then pack to fp16 A fragments
__device__ __forceinline__ void ss_pack(const float* acc, uint32_t* a) {
    #pragma unroll
    for (int p = 0; p < 8; p++) {
        float e0 = softsign_f(acc[2 * p]);
        float e1 = softsign_f(acc[2 * p + 1]);
        a[p] = cvt_f16x2(e1, e0);
    }
}

__global__ __launch_bounds__(NTHREADS, 2)
void actuator_hmma_kernel(const float* __restrict__ x,
                          const float* __restrict__ W1,
                          const float* __restrict__ b1,
                          const float* __restrict__ Wh,
                          const float* __restrict__ bh,
                          const float* __restrict__ Wout,
                          const float* __restrict__ bout,
                          float* __restrict__ out,
                          int B, int npairs)
{
    extern __shared__ char smem[];
    u64*   sFRAG = (u64*)(smem + SM_FRAG);
    float* sW1   = (float*)(smem + SM_W1);
    float* sB1   = (float*)(smem + SM_B1);
    float* sBH   = (float*)(smem + SM_BH);
    float* sWOUT = (float*)(smem + SM_WOUT);
    float* sBOUT = (float*)(smem + SM_BOUT);

    const int tid = threadIdx.x;

    for (int i = tid; i < 192; i += NTHREADS) sW1[i] = W1[i];
    for (int i = tid; i < 32;  i += NTHREADS) sB1[i] = b1[i];
    for (int i = tid; i < 608; i += NTHREADS) sBH[i] = bh[i];
    for (int i = tid; i < 32;  i += NTHREADS) sWOUT[i] = Wout[i];
    if (tid == 0) sBOUT[0] = bout[0];

    // stage hidden weights as per-thread fp16 B fragments, hi & lo
    // slot = ((l*16 + combo)*32 + lane), combo = term*8 + ks*4 + nb
    for (int idx = tid; idx < 19 * 16 * 32; idx += NTHREADS) {
        int lane  = idx & 31;
        int combo = (idx >> 5) & 15;
        int l     = idx >> 9;
        int nb    = combo & 3;
        int ks    = (combo >> 2) & 1;
        int term  = combo >> 3;            // 0 = Whi, 1 = Wlo
        int col   = nb * 8 + (lane >> 2);
        int qq    = lane & 3;
        int k0    = ks * 16 + qq * 2;

        const float* Wl = Wh + l * 1024;
        float w0 = Wl[(k0 + 0) * 32 + col];
        float w1 = Wl[(k0 + 1) * 32 + col];
        float w2 = Wl[(k0 + 8) * 32 + col];
        float w3 = Wl[(k0 + 9) * 32 + col];

        uint32_t rb0, rb1;
        if (term == 0) {
            rb0 = cvt_f16x2(w1, w0);
            rb1 = cvt_f16x2(w3, w2);
        } else {
            float r0 = w0 - __half2float(__float2half_rn(w0));
            float r1 = w1 - __half2float(__float2half_rn(w1));
            float r2 = w2 - __half2float(__float2half_rn(w2));
            float r3 = w3 - __half2float(__float2half_rn(w3));
            rb0 = cvt_f16x2(r1, r0);
            rb1 = cvt_f16x2(r3, r2);
        }
        sFRAG[idx] = ((u64)rb1 << 32) | rb0;
    }
    __syncthreads();

    const int wid  = tid >> 5;
    const int lane = tid & 31;
    const int g    = lane >> 2;
    const int q    = lane & 3;

    const float bias_out = sBOUT[0];

    for (int pair = blockIdx.x * NWARPS + wid; pair < npairs;
         pair += gridDim.x * NWARPS) {

        int base = pair * 32;
        int rA0 = base + g,      rA1 = base + 8 + g;
        int rB0 = base + 16 + g, rB1 = base + 24 + g;
        int cA0 = min(rA0, B - 1), cA1 = min(rA1, B - 1);
        int cB0 = min(rB0, B - 1), cB1 = min(rB1, B - 1);

        // acc holds RAW pre-activations at layer boundaries
        float acc0[16], acc1[16];

        // ---- layer 1 (6 -> 32), fp32 SIMT: raw preactivations ----
        {
            float x0[6], x1[6], x2[6], x3[6];
            const float* p0 = x + (long long)cA0 * 6;
            const float* p1 = x + (long long)cA1 * 6;
            const float* p2 = x + (long long)cB0 * 6;
            const float* p3 = x + (long long)cB1 * 6;
            #pragma unroll
            for (int i = 0; i < 6; i++) {
                x0[i] = __ldg(p0 + i); x1[i] = __ldg(p1 + i);
                x2[i] = __ldg(p2 + i); x3[i] = __ldg(p3 + i);
            }
            #pragma unroll
            for (int nb = 0; nb < 4; nb++) {
                int c0 = nb * 8 + q * 2;
                float b0 = sB1[c0], b1v = sB1[c0 + 1];
                float s00 = b0, s01 = b1v, s10 = b0, s11 = b1v;
                float t00 = b0, t01 = b1v, t10 = b0, t11 = b1v;
                #pragma unroll
                for (int i = 0; i < 6; i++) {
                    float w0 = sW1[i * 32 + c0], w1 = sW1[i * 32 + c0 + 1];
                    s00 += x0[i] * w0; s01 += x0[i] * w1;
                    s10 += x1[i] * w0; s11 += x1[i] * w1;
                    t00 += x2[i] * w0; t01 += x2[i] * w1;
                    t10 += x3[i] * w0; t11 += x3[i] * w1;
                }
                acc0[nb*4+0] = s00; acc0[nb*4+1] = s01;
                acc0[nb*4+2] = s10; acc0[nb*4+3] = s11;
                acc1[nb*4+0] = t00; acc1[nb*4+1] = t01;
                acc1[nb*4+2] = t10; acc1[nb*4+3] = t11;
            }
        }

        // ---- 19 hidden layers: 2-term fp16 HMMA (Ahi*Whi + Ahi*Wlo) ----
        for (int l = 0; l < 19; l++) {
            const u64* fl = sFRAG + l * 512 + lane;
            u64 Bf[16];
            #pragma unroll
            for (int c = 0; c < 16; c++) Bf[c] = fl[c * 32];

            uint32_t a0v[8], a1v[8];
            ss_pack(acc0, a0v);
            ss_pack(acc1, a1v);

            const float2* blp = (const float2*)(sBH + l * 32);

            #pragma unroll
            for (int ks = 0; ks < 2; ks++) {
                const uint32_t* A0 = a0v + ks * 4;
                const uint32_t* A1 = a1v + ks * 4;

                // term 0: Ahi * Whi  (bias-init on ks0)
                #pragma unroll
                for (int nb = 0; nb < 4; nb++) {
                    u64 w = Bf[ks * 4 + nb];
                    uint32_t b0 = (uint32_t)w, b1 = (uint32_t)(w >> 32);
                    if (ks == 0) {
                        float2 bb = blp[nb * 4 + q];
                        mma_f16_init(acc0 + nb * 4, A0[0], A0[1], A0[2], A0[3],
                                     b0, b1, bb.x, bb.y);
                        mma_f16_init(acc1 + nb * 4, A1[0], A1[1], A1[2], A1[3],
                                     b0, b1, bb.x, bb.y);
                    } else {
                        mma_f16(acc0 + nb * 4, A0[0], A0[1], A0[2], A0[3], b0, b1);
                        mma_f16(acc1 + nb * 4, A1[0], A1[1], A1[2], A1[3], b0, b1);
                    }
                }
                // term 1: Ahi * Wlo
                #pragma unroll
                for (int nb = 0; nb < 4; nb++) {
                    u64 w = Bf[8 + ks * 4 + nb];
                    uint32_t b0 = (uint32_t)w, b1 = (uint32_t)(w >> 32);
                    mma_f16(acc0 + nb * 4, A0[0], A0[1], A0[2], A0[3], b0, b1);
                    mma_f16(acc1 + nb * 4, A1[0], A1[1], A1[2], A1[3], b0, b1);
                }
            }
        }

        // ---- final softsign + output layer (32 -> 1) + quad reduction ----
        float pA0 = 0.0f, pA1 = 0.0f, pB0 = 0.0f, pB1 = 0.0f;
        #pragma unroll
        for (int nb = 0; nb < 4; nb++) {
            int c0 = nb * 8 + q * 2;
            float w0 = sWOUT[c0], w1 = sWOUT[c0 + 1];
            pA0 += softsign_f(acc0[nb*4+0]) * w0 + softsign_f(acc0[nb*4+1]) * w1;
            pA1 += softsign_f(acc0[nb*4+2]) * w0 + softsign_f(acc0[nb*4+3]) * w1;
            pB0 += softsign_f(acc1[nb*4+0]) * w0 + softsign_f(acc1[nb*4+1]) * w1;
            pB1 += softsign_f(acc1[nb*4+2]) * w0 + softsign_f(acc1[nb*4+3]) * w1;
        }
        pA0 += __shfl_xor_sync(0xFFFFFFFFu, pA0, 1);
        pA0 += __shfl_xor_sync(0xFFFFFFFFu, pA0, 2);
        pA1 += __shfl_xor_sync(0xFFFFFFFFu, pA1, 1);
        pA1 += __shfl_xor_sync(0xFFFFFFFFu, pA1, 2);
        pB0 += __shfl_xor_sync(0xFFFFFFFFu, pB0, 1);
        pB0 += __shfl_xor_sync(0xFFFFFFFFu, pB0, 2);
        pB1 += __shfl_xor_sync(0xFFFFFFFFu, pB1, 1);
        pB1 += __shfl_xor_sync(0xFFFFFFFFu, pB1, 2);
        if (q == 0) {
            if (rA0 < B) out[rA0] = pA0 + bias_out;
            if (rA1 < B) out[rA1] = pA1 + bias_out;
            if (rB0 < B) out[rB0] = pB0 + bias_out;
            if (rB1 < B) out[rB1] = pB1 + bias_out;
        }
    }
}

extern "C" void kernel_launch(void* const* d_in, const int* in_sizes, int n_in,
                              void* d_out, int out_size)
{
    const float* x    = (const float*)d_in[0];
    const float* W1   = (const float*)d_in[1];
    const float* b1   = (const float*)d_in[2];
    const float* Wh   = (const float*)d_in[3];
    const float* bh   = (const float*)d_in[4];
    const float* Wout = (const float*)d_in[5];
    const float* bout = (const float*)d_in[6];
    float* out = (float*)d_out;

    int B = in_sizes[0] / 6;
    int npairs = (B + 31) / 32;

    cudaFuncSetAttribute(actuator_hmma_kernel,
                         cudaFuncAttributeMaxDynamicSharedMemorySize, SM_TOTAL);

    int grid = 296;   // persistent: 2 CTAs/SM x 148 SMs
    actuator_hmma_kernel<<<grid, NTHREADS, SM_TOTAL>>>(
        x, W1, b1, Wh, bh, Wout, bout, out, B, npairs);
}